// round 15
// baseline (speedup 1.0000x reference)
#include <cuda_runtime.h>
#include <cuda_bf16.h>

// PositionalEncoding2D — persistent single-wave variant.
//   pe[i,b,2p]   = sin(x[i,b,0] * dt[p])
//   pe[i,b,2p+1] = cos(x[i,b,1] * dt[p]),  dt[p] = exp(p * -ln(1e4)/256)
//
// Input : x [65536 rows][2] fp32; Output: [65536 rows][512] fp32 = 128 MB.
// At the LTS store wall (~6.6 TB/s into L2, path-independent per R6/R7/R8).
// Last lever: the 4096-CTA launch ran ~3.5 waves; each wave tail drains store
// MLP and each transition costs ~2360 cyc. This version is persistent:
// grid = 148 SMs x 8 blocks = 1184 CTAs, one wave, warp-strided loop over
// row-pairs. dt values (one __expf + FMULs) are loop-invariant; stores from
// adjacent iterations are independent (MLP spans the loop boundary).
// (R13 run of this exact kernel died to container infra; resubmitting.)
//
// Layout per iteration: one warp = 2 rows; lane l owns quads {l,+32,+64,+96}
// of each row -> 8 coalesced STG.128.

#define NUM_ROWS   (2048 * 32)        // 65536
#define NUM_PAIRS  (NUM_ROWS / 2)     // 32768
#define GRID_BLKS  1184               // 148 SMs * 8 resident CTAs
#define WARPS_TOT  (GRID_BLKS * 8)    // 9472

__global__ __launch_bounds__(256)
void pe2d_kernel(const float4* __restrict__ x, float4* __restrict__ out) {
    const int warp0 = (blockIdx.x * 256 + threadIdx.x) >> 5;  // starting row-pair
    const int lane  = threadIdx.x & 31;

    // dt for quad t: exp(2t * C), C = -ln(1e4)/256  (loop-invariant)
    const float twoC = -9.210340371976184f / 128.0f;
    const float r    = 0.9646616199111993f;            // pair step 1e4^(-1/256)
    const float d0 = __expf((float)lane * twoC);       // quad lane
    const float d1 = d0 * 0.1f;                        // quad lane+32
    const float d2 = d1 * 0.1f;
    const float d3 = d2 * 0.1f;
    const float e0 = d0 * r, e1 = d1 * r, e2 = d2 * r, e3 = d3 * r;

    for (int wp = warp0; wp < NUM_PAIRS; wp += WARPS_TOT) {
        // Coords for rows 2wp, 2wp+1 (uniform within warp)
        const float4 xy2 = __ldg(x + wp);
        float4* o = out + (size_t)wp * 256 + lane;

        float4 a;
        // row 0
        a.x = __sinf(xy2.x * d0); a.y = __cosf(xy2.y * d0);
        a.z = __sinf(xy2.x * e0); a.w = __cosf(xy2.y * e0);
        o[0] = a;
        a.x = __sinf(xy2.x * d1); a.y = __cosf(xy2.y * d1);
        a.z = __sinf(xy2.x * e1); a.w = __cosf(xy2.y * e1);
        o[32] = a;
        a.x = __sinf(xy2.x * d2); a.y = __cosf(xy2.y * d2);
        a.z = __sinf(xy2.x * e2); a.w = __cosf(xy2.y * e2);
        o[64] = a;
        a.x = __sinf(xy2.x * d3); a.y = __cosf(xy2.y * d3);
        a.z = __sinf(xy2.x * e3); a.w = __cosf(xy2.y * e3);
        o[96] = a;
        // row 1
        a.x = __sinf(xy2.z * d0); a.y = __cosf(xy2.w * d0);
        a.z = __sinf(xy2.z * e0); a.w = __cosf(xy2.w * e0);
        o[128] = a;
        a.x = __sinf(xy2.z * d1); a.y = __cosf(xy2.w * d1);
        a.z = __sinf(xy2.z * e1); a.w = __cosf(xy2.w * e1);
        o[160] = a;
        a.x = __sinf(xy2.z * d2); a.y = __cosf(xy2.w * d2);
        a.z = __sinf(xy2.z * e2); a.w = __cosf(xy2.w * e2);
        o[192] = a;
        a.x = __sinf(xy2.z * d3); a.y = __cosf(xy2.w * d3);
        a.z = __sinf(xy2.z * e3); a.w = __cosf(xy2.w * e3);
        o[224] = a;
    }
}

extern "C" void kernel_launch(void* const* d_in, const int* in_sizes, int n_in,
                              void* d_out, int out_size) {
    const float4* x = (const float4*)d_in[0];
    float4* out = (float4*)d_out;
    pe2d_kernel<<<GRID_BLKS, 256>>>(x, out);   // one wave, persistent
}

// round 16
// speedup vs baseline: 1.0845x; 1.0845x over previous
#include <cuda_runtime.h>
#include <cuda_bf16.h>

// PositionalEncoding2D — FINAL kernel (champion, at the chip store wall).
//   pe[i,b,2p]   = sin(x[i,b,0] * dt[p])
//   pe[i,b,2p+1] = cos(x[i,b,1] * dt[p]),  dt[p] = exp(p * -ln(1e4)/256)
//
// Input : x  [65536 rows][2] fp32;  Output: [65536 rows][512] fp32 = 128 MB.
//
// Full campaign (GB300, sm_103a; kernel-time per ncu):
//   MLP=1  STG.128                     : 27.9 us
//   MLP=4  STG.128                     : 20.7 us
//   MLP=8  __stcs                      : 30.0 us  (.cs store path is slow)
//   MLP=8  plain STG.128  (THIS)       : 20.4 us  (reruns 20.4/21.4/20.4)
//   TMA bulk store (SMEM->GMEM)        : 21.5 us
//   STG.256 (st.global.v8.f32)         : 20.4 us
//   persistent 1-wave grid-stride      : 21.7 us  (wave transitions were free)
// 134 MB / 20.4 us = 6.57 TB/s into L2 ~= 95% of the measured LTS crossbar
// cap (~6300 B/cyc, path-independent across STG.128/STG.256/TMA). Output
// bytes fixed by the problem; compute pipes <25% busy. This is the floor.
//
// Layout: one warp = 2 rows. Lane l owns quads {l, l+32, l+64, l+96} per row
// -> 8 independent coalesced STG.128 in flight. dt by recurrence from one
// __expf: pair step r = 1e4^(-1/256); +32-quad step multiplies by 0.1 exactly.

#define NUM_ROWS (2048 * 32)   // 65536

__global__ __launch_bounds__(256)
void pe2d_kernel(const float4* __restrict__ x, float4* __restrict__ out) {
    const int warp = (blockIdx.x * 256 + threadIdx.x) >> 5;  // row-pair index
    const int lane = threadIdx.x & 31;

    // Coords for rows 2w and 2w+1: 4 contiguous floats (uniform in warp)
    const float4 xy2 = __ldg(x + warp);
    // row0: (xy2.x, xy2.y)   row1: (xy2.z, xy2.w)

    // dt for quad t: exp(2t * C), C = -ln(1e4)/256
    const float twoC = -9.210340371976184f / 128.0f;
    const float r    = 0.9646616199111993f;            // pair step 1e4^(-1/256)
    const float d0 = __expf((float)lane * twoC);       // quad lane
    const float d1 = d0 * 0.1f;                        // quad lane+32
    const float d2 = d1 * 0.1f;
    const float d3 = d2 * 0.1f;
    const float e0 = d0 * r, e1 = d1 * r, e2 = d2 * r, e3 = d3 * r;

    float4* o = out + (size_t)warp * 256 + lane;

    float4 a;
    // row 0
    a.x = __sinf(xy2.x * d0); a.y = __cosf(xy2.y * d0);
    a.z = __sinf(xy2.x * e0); a.w = __cosf(xy2.y * e0);
    o[0] = a;
    a.x = __sinf(xy2.x * d1); a.y = __cosf(xy2.y * d1);
    a.z = __sinf(xy2.x * e1); a.w = __cosf(xy2.y * e1);
    o[32] = a;
    a.x = __sinf(xy2.x * d2); a.y = __cosf(xy2.y * d2);
    a.z = __sinf(xy2.x * e2); a.w = __cosf(xy2.y * e2);
    o[64] = a;
    a.x = __sinf(xy2.x * d3); a.y = __cosf(xy2.y * d3);
    a.z = __sinf(xy2.x * e3); a.w = __cosf(xy2.y * e3);
    o[96] = a;
    // row 1
    a.x = __sinf(xy2.z * d0); a.y = __cosf(xy2.w * d0);
    a.z = __sinf(xy2.z * e0); a.w = __cosf(xy2.w * e0);
    o[128] = a;
    a.x = __sinf(xy2.z * d1); a.y = __cosf(xy2.w * d1);
    a.z = __sinf(xy2.z * e1); a.w = __cosf(xy2.w * e1);
    o[160] = a;
    a.x = __sinf(xy2.z * d2); a.y = __cosf(xy2.w * d2);
    a.z = __sinf(xy2.z * e2); a.w = __cosf(xy2.w * e2);
    o[192] = a;
    a.x = __sinf(xy2.z * d3); a.y = __cosf(xy2.w * d3);
    a.z = __sinf(xy2.z * e3); a.w = __cosf(xy2.w * e3);
    o[224] = a;
}

extern "C" void kernel_launch(void* const* d_in, const int* in_sizes, int n_in,
                              void* d_out, int out_size) {
    const float4* x = (const float4*)d_in[0];
    float4* out = (float4*)d_out;
    // 65536 rows, 2 rows/warp, 8 warps/block -> 4096 blocks
    pe2d_kernel<<<NUM_ROWS / 16, 256>>>(x, out);
}